// round 8
// baseline (speedup 1.0000x reference)
#include <cuda_runtime.h>
#include <math.h>

#define TINF 3.0e38f
#define TT   1024
#define BB   32
#define DDIM 64
#define RS   1024        // floats per diag row (128B-aligned rows)
#define DROWS 2072       // 2047 used + pad (max row touched = 2071)

// Diag-major cost [b][d][j]. Valid cells written by cost_kernel; invalid cells
// and tail rows pre-filled TINF by init_kernel. 269 MB.
__device__ float g_cost[(size_t)BB * DROWS * RS];
__device__ float g_n2[2 * BB * TT];
__device__ float g_bdist[BB];
__device__ __align__(16) float g_tinf[4] = {3.0e38f, 3.0e38f, 3.0e38f, 3.0e38f};

// ---------------------------------------------------------------------------
// Kernel 0: TINF only where needed — each diag row's invalid region is one
// contiguous run.
// ---------------------------------------------------------------------------
__global__ void init_kernel() {
    int d = blockIdx.x, b = blockIdx.y;
    float* row = g_cost + ((size_t)b * DROWS + d) * RS;
    int s, e;
    if (d < 1023)        { s = d + 1; e = 1024; }
    else if (d == 1023)  { return; }
    else if (d <= 2046)  { s = 0; e = d - 1023; }
    else                 { s = 0; e = 1024; }
    for (int j = s + threadIdx.x; j < e; j += 256) row[j] = TINF;
}

// ---------------------------------------------------------------------------
// Kernel 1: squared row norms. One warp per 64-dim row.
// ---------------------------------------------------------------------------
__global__ void norms_kernel(const float* __restrict__ pred,
                             const float* __restrict__ targ) {
    int gw   = (blockIdx.x * blockDim.x + threadIdx.x) >> 5;
    int lane = threadIdx.x & 31;
    if (gw >= 2 * BB * TT) return;
    const float* src = (gw < BB * TT) ? (pred + (size_t)gw * DDIM)
                                      : (targ + (size_t)(gw - BB * TT) * DDIM);
    float x0 = src[lane], x1 = src[lane + 32];
    float s = x0 * x0 + x1 * x1;
    #pragma unroll
    for (int o = 16; o > 0; o >>= 1) s += __shfl_down_sync(0xffffffffu, s, o);
    if (lane == 0) g_n2[gw] = s;
}

// ---------------------------------------------------------------------------
// Kernel 2: TF32 tensor-core cost tiles (unchanged from R7).
// ---------------------------------------------------------------------------
__device__ __forceinline__ unsigned f2tf(float x) {
    unsigned u;
    asm("cvt.rna.tf32.f32 %0, %1;" : "=r"(u) : "f"(x));
    return u;
}
__device__ __forceinline__ void mma_tf32(float c[4], const unsigned a[4],
                                         const unsigned b[2]) {
    asm volatile(
        "mma.sync.aligned.m16n8k8.row.col.f32.tf32.tf32.f32 "
        "{%0,%1,%2,%3}, {%4,%5,%6,%7}, {%8,%9}, {%0,%1,%2,%3};"
        : "+f"(c[0]), "+f"(c[1]), "+f"(c[2]), "+f"(c[3])
        : "r"(a[0]), "r"(a[1]), "r"(a[2]), "r"(a[3]), "r"(b[0]), "r"(b[1]));
}

#define SKP 36   // smem k-stride (32 + 4 pad)

__global__ void __launch_bounds__(256, 2) cost_kernel(const float* __restrict__ pred,
                                                      const float* __restrict__ targ) {
    int b  = blockIdx.z;
    int i0 = blockIdx.y * 128, j0 = blockIdx.x * 128;
    const float* A  = pred + (size_t)b * TT * DDIM;
    const float* Bm = targ + (size_t)b * TT * DDIM;

    __shared__ __align__(16) float smbuf[2 * 128 * SKP];   // 36864 B
    float* sA = smbuf;
    float* sB = smbuf + 128 * SKP;
    float* Cs = smbuf;                                     // reused in epilogue

    int tid  = threadIdx.x;
    int lane = tid & 31, w = tid >> 5;
    int g    = lane >> 2, tig = lane & 3;
    int wm   = (w & 3) * 32, wn = (w >> 2) * 64;

    float c[2][8][4];
    #pragma unroll
    for (int mt = 0; mt < 2; ++mt)
        #pragma unroll
        for (int nt = 0; nt < 8; ++nt)
            #pragma unroll
            for (int e = 0; e < 4; ++e) c[mt][nt][e] = 0.f;

    int lr = tid >> 1;                 // tile row 0..127
    int lk = (tid & 1) * 16;           // k-offset 0 or 16 within 32-chunk
    const float* ga = A  + (size_t)(i0 + lr) * DDIM + lk;
    const float* gb = Bm + (size_t)(j0 + lr) * DDIM + lk;

    #pragma unroll 1
    for (int kc = 0; kc < 64; kc += 32) {
        #pragma unroll
        for (int c4 = 0; c4 < 4; ++c4) {
            float4 va = *(const float4*)(ga + kc + c4 * 4);
            float4 vb = *(const float4*)(gb + kc + c4 * 4);
            int o = lr * SKP + lk + c4 * 4;
            sA[o + 0] = __uint_as_float(f2tf(va.x));
            sA[o + 1] = __uint_as_float(f2tf(va.y));
            sA[o + 2] = __uint_as_float(f2tf(va.z));
            sA[o + 3] = __uint_as_float(f2tf(va.w));
            sB[o + 0] = __uint_as_float(f2tf(vb.x));
            sB[o + 1] = __uint_as_float(f2tf(vb.y));
            sB[o + 2] = __uint_as_float(f2tf(vb.z));
            sB[o + 3] = __uint_as_float(f2tf(vb.w));
        }
        __syncthreads();

        #pragma unroll
        for (int ks = 0; ks < 32; ks += 8) {
            unsigned af[2][4], bf[8][2];
            #pragma unroll
            for (int mt = 0; mt < 2; ++mt) {
                int mr = wm + mt * 16;
                af[mt][0] = __float_as_uint(sA[(mr + g)     * SKP + ks + tig]);
                af[mt][1] = __float_as_uint(sA[(mr + g + 8) * SKP + ks + tig]);
                af[mt][2] = __float_as_uint(sA[(mr + g)     * SKP + ks + tig + 4]);
                af[mt][3] = __float_as_uint(sA[(mr + g + 8) * SKP + ks + tig + 4]);
            }
            #pragma unroll
            for (int nt = 0; nt < 8; ++nt) {
                int nr = wn + nt * 8 + g;
                bf[nt][0] = __float_as_uint(sB[nr * SKP + ks + tig]);
                bf[nt][1] = __float_as_uint(sB[nr * SKP + ks + tig + 4]);
            }
            #pragma unroll
            for (int mt = 0; mt < 2; ++mt)
                #pragma unroll
                for (int nt = 0; nt < 8; ++nt)
                    mma_tf32(c[mt][nt], af[mt], bf[nt]);
        }
        __syncthreads();
    }

    float a2v[2][2], b2v[8][2];
    #pragma unroll
    for (int mt = 0; mt < 2; ++mt) {
        a2v[mt][0] = g_n2[b * TT + i0 + wm + mt * 16 + g];
        a2v[mt][1] = g_n2[b * TT + i0 + wm + mt * 16 + g + 8];
    }
    #pragma unroll
    for (int nt = 0; nt < 8; ++nt) {
        b2v[nt][0] = g_n2[BB * TT + b * TT + j0 + wn + nt * 8 + 2 * tig];
        b2v[nt][1] = g_n2[BB * TT + b * TT + j0 + wn + nt * 8 + 2 * tig + 1];
    }

    float* out = g_cost + (size_t)b * DROWS * RS;

    #pragma unroll 1
    for (int qq = 0; qq < 4; ++qq) {
        int qi = qq >> 1, qj = qq & 1;
        __syncthreads();
        if ((w >> 2) == qj && ((w & 3) >> 1) == qi) {
            int mloc0 = ((w & 3) & 1) * 32;
            #pragma unroll
            for (int mt = 0; mt < 2; ++mt) {
                int ml = mloc0 + mt * 16 + g;
                #pragma unroll
                for (int nt = 0; nt < 8; ++nt) {
                    int nl = nt * 8 + 2 * tig;
                    float s0 = a2v[mt][0] + b2v[nt][0] - 2.0f * c[mt][nt][0];
                    float s1 = a2v[mt][0] + b2v[nt][1] - 2.0f * c[mt][nt][1];
                    float s2 = a2v[mt][1] + b2v[nt][0] - 2.0f * c[mt][nt][2];
                    float s3 = a2v[mt][1] + b2v[nt][1] - 2.0f * c[mt][nt][3];
                    Cs[ml * 66 + nl]           = sqrtf(fmaxf(s0, 1e-12f));
                    Cs[ml * 66 + nl + 1]       = sqrtf(fmaxf(s1, 1e-12f));
                    Cs[(ml + 8) * 66 + nl]     = sqrtf(fmaxf(s2, 1e-12f));
                    Cs[(ml + 8) * 66 + nl + 1] = sqrtf(fmaxf(s3, 1e-12f));
                }
            }
        }
        __syncthreads();

        int i0q = i0 + qi * 64, j0q = j0 + qj * 64;
        int D0 = i0q + j0q;
        for (int dd = w; dd < 127; dd += 8) {
            int jl = max(0, dd - 63);
            int jh = min(dd, 63);
            int L = jh - jl + 1;
            size_t gbase = (size_t)(D0 + dd) * RS + (size_t)(j0q + jl);
            for (int l = lane; l < L; l += 32) {
                int j = jl + l;
                out[gbase + l] = Cs[(dd - j) * 66 + j];
            }
        }
    }
}

// ---------------------------------------------------------------------------
// Kernel 3: wavefront DP, EIGHT diagonals per superstep (258 supersteps).
// 256 threads x 4 cols, extended window 12 (halo 8 from threads t-1, t-2 via
// the exchange buffers). Own cost quads ride a distance-1 double-buffered
// register ring; halo cost quads are JIT LDGs that hit L1 (lines were fetched
// by the prefetch stream one superstep earlier). TINF padding => no masks;
// sp[*][0] preset TINF and never written => t=0/t=1 halos are natural.
// ---------------------------------------------------------------------------
__global__ void __launch_bounds__(256, 1) dp_kernel() {
    int b  = blockIdx.x;
    int t  = threadIdx.x;
    int j0 = t << 2;
    const float* SCo = g_cost + (size_t)b * DROWS * RS + j0;
    const float* PH0 = (t >= 2) ? (SCo - 8) : g_tinf;   // halo cols j0-8..j0-5
    const size_t H0  = (t >= 2) ? (size_t)RS : 0;
    const float* PH1 = (t >= 1) ? (SCo - 4) : g_tinf;   // halo cols j0-4..j0-1
    const size_t H1  = (t >= 1) ? (size_t)RS : 0;

    __shared__ float4 sp[2][257], sq[2][257];
    for (int i = t; i < 2 * 257; i += 256) {
        (&sp[0][0])[i] = make_float4(TINF, TINF, TINF, TINF);
        (&sq[0][0])[i] = make_float4(TINF, TINF, TINF, TINF);
    }
    __syncthreads();

    float p[4] = {TINF, TINF, TINF, TINF};   // diag d0-1, own cols
    float q[4] = {TINF, TINF, TINF, TINF};   // diag d0-2, own cols
    float res = 0.f;
    const int tm1 = (t > 0) ? t - 1 : 0;

    float4 CO[2][8];                          // own quads, double-buffered
    #pragma unroll
    for (int k = 0; k < 8; ++k)
        CO[0][k] = *(const float4*)(SCo + (size_t)k * RS);

    // 258 supersteps x 8 diagonals = 2064 (rows >= 2047 are TINF pad).
    for (int db = 0; db < 2064; db += 16) {
        #pragma unroll
        for (int u = 0; u < 2; ++u) {
            const int d0  = db + 8 * u;
            const int cur = u, pre = u ^ 1;

            #pragma unroll
            for (int k = 0; k < 8; ++k)       // prefetch next superstep's own
                CO[pre][k] = *(const float4*)(SCo + (size_t)(d0 + 8 + k) * RS);

            float4 hpA = sp[cur][tm1], hpB = sp[cur][t];
            float4 hqA = sq[cur][tm1], hqB = sq[cur][t];

            float P[12] = {hpA.x, hpA.y, hpA.z, hpA.w,
                           hpB.x, hpB.y, hpB.z, hpB.w, p[0], p[1], p[2], p[3]};
            float Q[12] = {hqA.x, hqA.y, hqA.z, hqA.w,
                           hqB.x, hqB.y, hqB.z, hqB.w, q[0], q[1], q[2], q[3]};
            if (d0 == 0 && t == 0) Q[7] = -TINF;   // seed: virtual ca[-1][-1]

            // Cost rows (extended i = col - j0 + 8). Level l reads i >= l+1.
            float C[8][12];
            #pragma unroll
            for (int l = 0; l < 8; ++l) {
                float4 ov = CO[cur][l];
                C[l][8] = ov.x; C[l][9] = ov.y; C[l][10] = ov.z; C[l][11] = ov.w;
            }
            #pragma unroll
            for (int l = 0; l < 7; ++l) {     // i=4..7 needed for l<=6
                float4 h = *(const float4*)(PH1 + (size_t)(d0 + l) * H1);
                C[l][4] = h.x; C[l][5] = h.y; C[l][6] = h.z; C[l][7] = h.w;
            }
            #pragma unroll
            for (int l = 0; l < 3; ++l) {     // i=1..3 needed for l<=2
                float4 h = *(const float4*)(PH0 + (size_t)(d0 + l) * H0);
                C[l][0] = h.x; C[l][1] = h.y; C[l][2] = h.z; C[l][3] = h.w;
            }

            float L0[12], L1[12], L2[12], L3[12], L4[12], L5[12], L6[12], L7[12];
            #pragma unroll
            for (int i = 1; i < 12; ++i)
                L0[i] = fmaxf(C[0][i], fminf(fminf(P[i],  P[i-1]),  Q[i-1]));
            #pragma unroll
            for (int i = 2; i < 12; ++i)
                L1[i] = fmaxf(C[1][i], fminf(fminf(L0[i], L0[i-1]), P[i-1]));
            #pragma unroll
            for (int i = 3; i < 12; ++i)
                L2[i] = fmaxf(C[2][i], fminf(fminf(L1[i], L1[i-1]), L0[i-1]));
            #pragma unroll
            for (int i = 4; i < 12; ++i)
                L3[i] = fmaxf(C[3][i], fminf(fminf(L2[i], L2[i-1]), L1[i-1]));
            #pragma unroll
            for (int i = 5; i < 12; ++i)
                L4[i] = fmaxf(C[4][i], fminf(fminf(L3[i], L3[i-1]), L2[i-1]));
            #pragma unroll
            for (int i = 6; i < 12; ++i)
                L5[i] = fmaxf(C[5][i], fminf(fminf(L4[i], L4[i-1]), L3[i-1]));
            #pragma unroll
            for (int i = 7; i < 12; ++i)
                L6[i] = fmaxf(C[6][i], fminf(fminf(L5[i], L5[i-1]), L4[i-1]));
            #pragma unroll
            for (int i = 8; i < 12; ++i)
                L7[i] = fmaxf(C[7][i], fminf(fminf(L6[i], L6[i-1]), L5[i-1]));

            sp[pre][t + 1] = make_float4(L7[8], L7[9], L7[10], L7[11]);
            sq[pre][t + 1] = make_float4(L6[8], L6[9], L6[10], L6[11]);
            if (d0 == 2040) res = L6[11];     // diag 2046, col 1023 @ t=255
            __syncthreads();

            p[0] = L7[8]; p[1] = L7[9]; p[2] = L7[10]; p[3] = L7[11];
            q[0] = L6[8]; q[1] = L6[9]; q[2] = L6[10]; q[3] = L6[11];
        }
    }

    if (t == 255) g_bdist[b] = res;
}

// ---------------------------------------------------------------------------
// Kernel 4: mean over batches.
// ---------------------------------------------------------------------------
__global__ void reduce_kernel(float* out) {
    float v = g_bdist[threadIdx.x];
    #pragma unroll
    for (int o = 16; o > 0; o >>= 1) v += __shfl_down_sync(0xffffffffu, v, o);
    if (threadIdx.x == 0) out[0] = v * (1.0f / BB);
}

// ---------------------------------------------------------------------------
extern "C" void kernel_launch(void* const* d_in, const int* in_sizes, int n_in,
                              void* d_out, int out_size) {
    const float* pred = (const float*)d_in[0];
    const float* targ = (const float*)d_in[1];
    (void)in_sizes; (void)n_in; (void)out_size;

    dim3 ig(DROWS, BB);
    init_kernel<<<ig, 256>>>();
    norms_kernel<<<8192, 256>>>(pred, targ);
    dim3 cg(8, 8, 32);
    cost_kernel<<<cg, 256>>>(pred, targ);
    dp_kernel<<<32, 256>>>();
    reduce_kernel<<<1, 32>>>((float*)d_out);
}

// round 9
// speedup vs baseline: 1.2093x; 1.2093x over previous
#include <cuda_runtime.h>
#include <math.h>

#define TINF 3.0e38f
#define TT   1024
#define BB   32
#define DDIM 64
#define RS   1024        // floats per diag row (128B-aligned rows)
#define DROWS 2096       // 2047 used + prefetch pad (max row touched = 2095)

// Diag-major cost [b][d][j]. Valid cells written by cost_kernel; invalid cells
// pre-filled TINF by init_kernel (rows >= 2047 left uninitialized: provably
// never influence the result, fmin/fmax are NaN-safe). 274 MB.
__device__ float g_cost[(size_t)BB * DROWS * RS];
__device__ float g_n2[2 * BB * TT];
__device__ float g_bdist[BB];
__device__ __align__(16) float g_tinf[4] = {3.0e38f, 3.0e38f, 3.0e38f, 3.0e38f};

// ---------------------------------------------------------------------------
// Kernel 0: TINF only where needed — each diag row's invalid region is one
// contiguous run. Launched for d in [0, 2047) only.
// ---------------------------------------------------------------------------
__global__ void init_kernel() {
    int d = blockIdx.x, b = blockIdx.y;
    float* row = g_cost + ((size_t)b * DROWS + d) * RS;
    int s, e;
    if (d < 1023)        { s = d + 1; e = 1024; }
    else if (d == 1023)  { return; }
    else                 { s = 0; e = d - 1023; }
    for (int j = s + threadIdx.x; j < e; j += 256) row[j] = TINF;
}

// ---------------------------------------------------------------------------
// Kernel 1: squared row norms. One warp per 64-dim row.
// ---------------------------------------------------------------------------
__global__ void norms_kernel(const float* __restrict__ pred,
                             const float* __restrict__ targ) {
    int gw   = (blockIdx.x * blockDim.x + threadIdx.x) >> 5;
    int lane = threadIdx.x & 31;
    if (gw >= 2 * BB * TT) return;
    const float* src = (gw < BB * TT) ? (pred + (size_t)gw * DDIM)
                                      : (targ + (size_t)(gw - BB * TT) * DDIM);
    float x0 = src[lane], x1 = src[lane + 32];
    float s = x0 * x0 + x1 * x1;
    #pragma unroll
    for (int o = 16; o > 0; o >>= 1) s += __shfl_down_sync(0xffffffffu, s, o);
    if (lane == 0) g_n2[gw] = s;
}

// ---------------------------------------------------------------------------
// Kernel 2: TF32 tensor-core cost tiles (unchanged from R7).
// ---------------------------------------------------------------------------
__device__ __forceinline__ unsigned f2tf(float x) {
    unsigned u;
    asm("cvt.rna.tf32.f32 %0, %1;" : "=r"(u) : "f"(x));
    return u;
}
__device__ __forceinline__ void mma_tf32(float c[4], const unsigned a[4],
                                         const unsigned b[2]) {
    asm volatile(
        "mma.sync.aligned.m16n8k8.row.col.f32.tf32.tf32.f32 "
        "{%0,%1,%2,%3}, {%4,%5,%6,%7}, {%8,%9}, {%0,%1,%2,%3};"
        : "+f"(c[0]), "+f"(c[1]), "+f"(c[2]), "+f"(c[3])
        : "r"(a[0]), "r"(a[1]), "r"(a[2]), "r"(a[3]), "r"(b[0]), "r"(b[1]));
}

#define SKP 36   // smem k-stride (32 + 4 pad)

__global__ void __launch_bounds__(256, 2) cost_kernel(const float* __restrict__ pred,
                                                      const float* __restrict__ targ) {
    int b  = blockIdx.z;
    int i0 = blockIdx.y * 128, j0 = blockIdx.x * 128;
    const float* A  = pred + (size_t)b * TT * DDIM;
    const float* Bm = targ + (size_t)b * TT * DDIM;

    __shared__ __align__(16) float smbuf[2 * 128 * SKP];   // 36864 B
    float* sA = smbuf;
    float* sB = smbuf + 128 * SKP;
    float* Cs = smbuf;                                     // reused in epilogue

    int tid  = threadIdx.x;
    int lane = tid & 31, w = tid >> 5;
    int g    = lane >> 2, tig = lane & 3;
    int wm   = (w & 3) * 32, wn = (w >> 2) * 64;

    float c[2][8][4];
    #pragma unroll
    for (int mt = 0; mt < 2; ++mt)
        #pragma unroll
        for (int nt = 0; nt < 8; ++nt)
            #pragma unroll
            for (int e = 0; e < 4; ++e) c[mt][nt][e] = 0.f;

    int lr = tid >> 1;                 // tile row 0..127
    int lk = (tid & 1) * 16;           // k-offset 0 or 16 within 32-chunk
    const float* ga = A  + (size_t)(i0 + lr) * DDIM + lk;
    const float* gb = Bm + (size_t)(j0 + lr) * DDIM + lk;

    #pragma unroll 1
    for (int kc = 0; kc < 64; kc += 32) {
        #pragma unroll
        for (int c4 = 0; c4 < 4; ++c4) {
            float4 va = *(const float4*)(ga + kc + c4 * 4);
            float4 vb = *(const float4*)(gb + kc + c4 * 4);
            int o = lr * SKP + lk + c4 * 4;
            sA[o + 0] = __uint_as_float(f2tf(va.x));
            sA[o + 1] = __uint_as_float(f2tf(va.y));
            sA[o + 2] = __uint_as_float(f2tf(va.z));
            sA[o + 3] = __uint_as_float(f2tf(va.w));
            sB[o + 0] = __uint_as_float(f2tf(vb.x));
            sB[o + 1] = __uint_as_float(f2tf(vb.y));
            sB[o + 2] = __uint_as_float(f2tf(vb.z));
            sB[o + 3] = __uint_as_float(f2tf(vb.w));
        }
        __syncthreads();

        #pragma unroll
        for (int ks = 0; ks < 32; ks += 8) {
            unsigned af[2][4], bf[8][2];
            #pragma unroll
            for (int mt = 0; mt < 2; ++mt) {
                int mr = wm + mt * 16;
                af[mt][0] = __float_as_uint(sA[(mr + g)     * SKP + ks + tig]);
                af[mt][1] = __float_as_uint(sA[(mr + g + 8) * SKP + ks + tig]);
                af[mt][2] = __float_as_uint(sA[(mr + g)     * SKP + ks + tig + 4]);
                af[mt][3] = __float_as_uint(sA[(mr + g + 8) * SKP + ks + tig + 4]);
            }
            #pragma unroll
            for (int nt = 0; nt < 8; ++nt) {
                int nr = wn + nt * 8 + g;
                bf[nt][0] = __float_as_uint(sB[nr * SKP + ks + tig]);
                bf[nt][1] = __float_as_uint(sB[nr * SKP + ks + tig + 4]);
            }
            #pragma unroll
            for (int mt = 0; mt < 2; ++mt)
                #pragma unroll
                for (int nt = 0; nt < 8; ++nt)
                    mma_tf32(c[mt][nt], af[mt], bf[nt]);
        }
        __syncthreads();
    }

    float a2v[2][2], b2v[8][2];
    #pragma unroll
    for (int mt = 0; mt < 2; ++mt) {
        a2v[mt][0] = g_n2[b * TT + i0 + wm + mt * 16 + g];
        a2v[mt][1] = g_n2[b * TT + i0 + wm + mt * 16 + g + 8];
    }
    #pragma unroll
    for (int nt = 0; nt < 8; ++nt) {
        b2v[nt][0] = g_n2[BB * TT + b * TT + j0 + wn + nt * 8 + 2 * tig];
        b2v[nt][1] = g_n2[BB * TT + b * TT + j0 + wn + nt * 8 + 2 * tig + 1];
    }

    float* out = g_cost + (size_t)b * DROWS * RS;

    #pragma unroll 1
    for (int qq = 0; qq < 4; ++qq) {
        int qi = qq >> 1, qj = qq & 1;
        __syncthreads();
        if ((w >> 2) == qj && ((w & 3) >> 1) == qi) {
            int mloc0 = ((w & 3) & 1) * 32;
            #pragma unroll
            for (int mt = 0; mt < 2; ++mt) {
                int ml = mloc0 + mt * 16 + g;
                #pragma unroll
                for (int nt = 0; nt < 8; ++nt) {
                    int nl = nt * 8 + 2 * tig;
                    float s0 = a2v[mt][0] + b2v[nt][0] - 2.0f * c[mt][nt][0];
                    float s1 = a2v[mt][0] + b2v[nt][1] - 2.0f * c[mt][nt][1];
                    float s2 = a2v[mt][1] + b2v[nt][0] - 2.0f * c[mt][nt][2];
                    float s3 = a2v[mt][1] + b2v[nt][1] - 2.0f * c[mt][nt][3];
                    Cs[ml * 66 + nl]           = sqrtf(fmaxf(s0, 1e-12f));
                    Cs[ml * 66 + nl + 1]       = sqrtf(fmaxf(s1, 1e-12f));
                    Cs[(ml + 8) * 66 + nl]     = sqrtf(fmaxf(s2, 1e-12f));
                    Cs[(ml + 8) * 66 + nl + 1] = sqrtf(fmaxf(s3, 1e-12f));
                }
            }
        }
        __syncthreads();

        int i0q = i0 + qi * 64, j0q = j0 + qj * 64;
        int D0 = i0q + j0q;
        for (int dd = w; dd < 127; dd += 8) {
            int jl = max(0, dd - 63);
            int jh = min(dd, 63);
            int L = jh - jl + 1;
            size_t gbase = (size_t)(D0 + dd) * RS + (size_t)(j0q + jl);
            for (int l = lane; l < L; l += 32) {
                int j = jl + l;
                out[gbase + l] = Cs[(dd - j) * 66 + j];
            }
        }
    }
}

// ---------------------------------------------------------------------------
// Kernel 3: wavefront DP, 4 diagonals per superstep (R7 math, unchanged),
// cost prefetched FOUR supersteps ahead through a 5-deep register ring
// (16 rows in flight per thread — Little's-law fix; all indices static
// under the 10-superstep unroll = lcm(5, 2)).
// ---------------------------------------------------------------------------
__device__ __forceinline__ void superstep(
    int db, int t, int lane, const float4 co[4], const float4 chl[4],
    float p[4], float q[4],
    float4* spr, float4* sqr, float4* spw, float4* sqw, float& res)
{
    float4 hp4 = spr[t], hq4 = sqr[t];
    if (t == 0) {
        hp4.x = hp4.y = hp4.z = hp4.w = TINF;
        hq4.x = hq4.y = hq4.z = TINF;
        hq4.w = (db == 0) ? -TINF : TINF;   // seed: virtual ca[-1][-1]
    }
    float P[8] = {hp4.x, hp4.y, hp4.z, hp4.w, p[0], p[1], p[2], p[3]};   // diag db-1
    float Q[8] = {hq4.x, hq4.y, hq4.z, hq4.w, q[0], q[1], q[2], q[3]};   // diag db-2
    float CC[4][8];
    #pragma unroll
    for (int k = 0; k < 4; ++k) {
        float sx = __shfl_up_sync(0xffffffffu, co[k].x, 1);
        float sy = __shfl_up_sync(0xffffffffu, co[k].y, 1);
        float sz = __shfl_up_sync(0xffffffffu, co[k].z, 1);
        float sw = __shfl_up_sync(0xffffffffu, co[k].w, 1);
        CC[k][0] = lane ? sx : chl[k].x;
        CC[k][1] = lane ? sy : chl[k].y;
        CC[k][2] = lane ? sz : chl[k].z;
        CC[k][3] = lane ? sw : chl[k].w;
        CC[k][4] = co[k].x; CC[k][5] = co[k].y;
        CC[k][6] = co[k].z; CC[k][7] = co[k].w;
    }
    float A[8], B[8], C[8], D[8];
    #pragma unroll
    for (int i = 1; i < 8; ++i)
        A[i] = fmaxf(CC[0][i], fminf(fminf(P[i], P[i-1]), Q[i-1]));
    #pragma unroll
    for (int i = 2; i < 8; ++i)
        B[i] = fmaxf(CC[1][i], fminf(fminf(A[i], A[i-1]), P[i-1]));
    #pragma unroll
    for (int i = 3; i < 8; ++i)
        C[i] = fmaxf(CC[2][i], fminf(fminf(B[i], B[i-1]), A[i-1]));
    #pragma unroll
    for (int i = 4; i < 8; ++i)
        D[i] = fmaxf(CC[3][i], fminf(fminf(C[i], C[i-1]), B[i-1]));

    spw[t + 1] = make_float4(D[4], D[5], D[6], D[7]);
    sqw[t + 1] = make_float4(C[4], C[5], C[6], C[7]);
    if (db == 2044) res = C[7];          // diag 2046, col 1023 @ t=255
    __syncthreads();

    p[0] = D[4]; p[1] = D[5]; p[2] = D[6]; p[3] = D[7];
    q[0] = C[4]; q[1] = C[5]; q[2] = C[6]; q[3] = C[7];
}

__global__ void __launch_bounds__(256, 1) dp_kernel() {
    int b    = blockIdx.x;
    int t    = threadIdx.x;
    int lane = t & 31;
    int j0   = t << 2;
    const float* SCo = g_cost + (size_t)b * DROWS * RS + j0;
    const float* SCh = (t == 0) ? g_tinf : (SCo - 4);   // lane-0 halo base
    const size_t HST = (t == 0) ? 0 : (size_t)RS;

    __shared__ float4 sp[2][257], sq[2][257];
    for (int i = t; i < 2 * 257; i += 256) {
        (&sp[0][0])[i] = make_float4(TINF, TINF, TINF, TINF);
        (&sq[0][0])[i] = make_float4(TINF, TINF, TINF, TINF);
    }
    __syncthreads();

    float p[4] = {TINF, TINF, TINF, TINF};
    float q[4] = {TINF, TINF, TINF, TINF};
    float res = 0.f;

    // 5-deep ring: slot s%5 holds superstep s's 4 cost rows. Fill ss 0..3.
    float4 CO[5][4], CHL[5][4];
    #pragma unroll
    for (int s = 0; s < 4; ++s)
        #pragma unroll
        for (int k = 0; k < 4; ++k)
            CO[s][k] = *(const float4*)(SCo + (size_t)(4 * s + k) * RS);
    if (lane == 0) {
        #pragma unroll
        for (int s = 0; s < 4; ++s)
            #pragma unroll
            for (int k = 0; k < 4; ++k)
                CHL[s][k] = *(const float4*)(SCh + (size_t)(4 * s + k) * HST);
    }

    // 2080 diagonals = 52 outer iters x 10 supersteps. Max row prefetched:
    // d0=2076 -> 2076+16+3 = 2095 < DROWS.
    for (int db = 0; db < 2080; db += 40) {
        #pragma unroll
        for (int u = 0; u < 10; ++u) {
            const int cur = u % 5;           // slot consumed this superstep
            const int pre = (u + 4) % 5;     // slot refilled for superstep u+4
            int dpre = db + 4 * u + 16;
            #pragma unroll
            for (int k = 0; k < 4; ++k)
                CO[pre][k] = *(const float4*)(SCo + (size_t)(dpre + k) * RS);
            if (lane == 0) {
                #pragma unroll
                for (int k = 0; k < 4; ++k)
                    CHL[pre][k] = *(const float4*)(SCh + (size_t)(dpre + k) * HST);
            }
            if (u % 2 == 0)
                superstep(db + 4 * u, t, lane, CO[cur], CHL[cur], p, q,
                          &sp[0][0], &sq[0][0], &sp[1][0], &sq[1][0], res);
            else
                superstep(db + 4 * u, t, lane, CO[cur], CHL[cur], p, q,
                          &sp[1][0], &sq[1][0], &sp[0][0], &sq[0][0], res);
        }
    }

    if (t == 255) g_bdist[b] = res;
}

// ---------------------------------------------------------------------------
// Kernel 4: mean over batches.
// ---------------------------------------------------------------------------
__global__ void reduce_kernel(float* out) {
    float v = g_bdist[threadIdx.x];
    #pragma unroll
    for (int o = 16; o > 0; o >>= 1) v += __shfl_down_sync(0xffffffffu, v, o);
    if (threadIdx.x == 0) out[0] = v * (1.0f / BB);
}

// ---------------------------------------------------------------------------
extern "C" void kernel_launch(void* const* d_in, const int* in_sizes, int n_in,
                              void* d_out, int out_size) {
    const float* pred = (const float*)d_in[0];
    const float* targ = (const float*)d_in[1];
    (void)in_sizes; (void)n_in; (void)out_size;

    dim3 ig(2047, BB);
    init_kernel<<<ig, 256>>>();
    norms_kernel<<<8192, 256>>>(pred, targ);
    dim3 cg(8, 8, 32);
    cost_kernel<<<cg, 256>>>(pred, targ);
    dp_kernel<<<32, 256>>>();
    reduce_kernel<<<1, 32>>>((float*)d_out);
}